// round 3
// baseline (speedup 1.0000x reference)
#include <cuda_runtime.h>
#include <math.h>

#define B_   8
#define N_   8192
#define C_   256
#define H_   128
#define W_   128
#define NH_  8
#define NP_  4
#define D_   32
#define HW_  (H_ * W_)
#define M_   (B_ * N_)      // 65536
#define P96  96
#define GK   256

// ---- scratch (static device allocations; no cudaMalloc anywhere) ----
__device__ float g_valt[(size_t)B_ * NH_ * HW_ * D_];   // (B,Hh,HW,D)
__device__ float g_params[(size_t)M_ * P96];            // [offsets(64) | attn logits(32)]
__device__ float g_agg[(size_t)M_ * C_];
__device__ float g_wcat[C_ * P96];
__device__ float g_bcat[P96];

// ---------------------------------------------------------------------------
__global__ void concat_w_kernel(const float* __restrict__ W_off,
                                const float* __restrict__ b_off,
                                const float* __restrict__ W_attn,
                                const float* __restrict__ b_attn) {
    int i = blockIdx.x * blockDim.x + threadIdx.x;
    if (i < C_ * P96) {
        int k = i / P96, j = i % P96;
        g_wcat[i] = (j < 64) ? W_off[k * 64 + j] : W_attn[k * 32 + (j - 64)];
    }
    if (i < P96) g_bcat[i] = (i < 64) ? b_off[i] : b_attn[i - 64];
}

// ---------------------------------------------------------------------------
// Transpose value (B, Hh*D, H*W) -> (B, Hh, H*W, D)
// ---------------------------------------------------------------------------
__global__ void transpose_val_kernel(const float* __restrict__ val) {
    __shared__ float t[32][33];
    int bh = blockIdx.y;
    int p0 = blockIdx.x * 32;
    const float* src = val + ((size_t)bh * 32) * HW_ + p0;
    for (int d = threadIdx.y; d < 32; d += 8)
        t[d][threadIdx.x] = src[(size_t)d * HW_ + threadIdx.x];
    __syncthreads();
    float* dst = g_valt + (size_t)bh * HW_ * D_ + (size_t)p0 * D_;
    for (int dp = threadIdx.y; dp < 32; dp += 8)
        dst[(size_t)dp * D_ + threadIdx.x] = t[threadIdx.x][dp];
}

// ---------------------------------------------------------------------------
// tf32x3 tensor-core GEMM (fp32-accurate): C[M,Nn] = A[M,256] @ B[256,Nn]+bias
// Each operand split v = hi + lo (cvt.rna.tf32); acc += hi*hi + hi*lo + lo*hi.
// 128x128 CTA tile, BK=16, 8 warps (2x4), warp tile 64x32 via m16n8k8 tf32.
// Smem holds (hi,lo) as float2:
//   As2 k-major [16][132]: frag bank = (8k+2m)%32 -> 8q+2r, conflict-free.
//   Bs2 n-major [16][140]: frag bank = (24k+2n)%32 -> 24q+2r, conflict-free.
// ---------------------------------------------------------------------------
__device__ __forceinline__ float2 split_tf32(float v) {
    unsigned hi_u;
    asm("cvt.rna.tf32.f32 %0, %1;" : "=r"(hi_u) : "f"(v));
    float hi = __uint_as_float(hi_u);
    float lo = v - hi;
    unsigned lo_u;
    asm("cvt.rna.tf32.f32 %0, %1;" : "=r"(lo_u) : "f"(lo));
    return make_float2(hi, __uint_as_float(lo_u));
}

__device__ __forceinline__ void mma_tf32(float* d,
                                         float a0, float a1, float a2, float a3,
                                         float b0, float b1) {
    unsigned ua0 = __float_as_uint(a0), ua1 = __float_as_uint(a1);
    unsigned ua2 = __float_as_uint(a2), ua3 = __float_as_uint(a3);
    unsigned ub0 = __float_as_uint(b0), ub1 = __float_as_uint(b1);
    asm volatile(
        "mma.sync.aligned.m16n8k8.row.col.f32.tf32.tf32.f32 "
        "{%0,%1,%2,%3}, {%4,%5,%6,%7}, {%8,%9}, {%0,%1,%2,%3};\n"
        : "+f"(d[0]), "+f"(d[1]), "+f"(d[2]), "+f"(d[3])
        : "r"(ua0), "r"(ua1), "r"(ua2), "r"(ua3), "r"(ub0), "r"(ub1));
}

__global__ __launch_bounds__(256, 1)
void tf32x3_gemm_kernel(const float* __restrict__ A,
                        const float* __restrict__ Bw,
                        const float* __restrict__ bias,
                        float* __restrict__ Cm, int Nn) {
    __shared__ float2 As2[16][132];   // [k][m]
    __shared__ float2 Bs2[16][140];   // [k][n]

    const int tid  = threadIdx.x;
    const int row0 = blockIdx.y * 128;
    const int col0 = blockIdx.x * 128;
    const int wid  = tid >> 5;
    const int lane = tid & 31;
    const int wm   = (wid >> 2) * 64;
    const int wn   = (wid & 3) * 32;
    const int r    = lane >> 2;
    const int q    = lane & 3;

    float acc[4][4][4];
#pragma unroll
    for (int mi = 0; mi < 4; mi++)
#pragma unroll
        for (int ni = 0; ni < 4; ni++)
#pragma unroll
            for (int v = 0; v < 4; v++) acc[mi][ni][v] = 0.f;

    const int am  = tid >> 1;          // 0..127
    const int akh = (tid & 1) * 8;     // 0 or 8
    const int bk  = tid >> 5;          // 0..7 (+8 second pass)
    const int bn4 = (tid & 31) * 4;    // 0..124

    for (int k0 = 0; k0 < GK; k0 += 16) {
        // ---- stage A (transpose m-major -> k-major, split hi/lo) ----
#pragma unroll
        for (int j = 0; j < 2; j++) {
            float4 v = *(const float4*)&A[(size_t)(row0 + am) * GK + k0 + akh + j * 4];
            As2[akh + j * 4 + 0][am] = split_tf32(v.x);
            As2[akh + j * 4 + 1][am] = split_tf32(v.y);
            As2[akh + j * 4 + 2][am] = split_tf32(v.z);
            As2[akh + j * 4 + 3][am] = split_tf32(v.w);
        }
        // ---- stage B (n-major, split hi/lo, paired float4 stores) ----
#pragma unroll
        for (int j = 0; j < 2; j++) {
            int kk = bk + j * 8;
            float4 v = make_float4(0.f, 0.f, 0.f, 0.f);
            if (col0 + bn4 < Nn)
                v = *(const float4*)&Bw[(size_t)(k0 + kk) * Nn + col0 + bn4];
            float2 s0 = split_tf32(v.x), s1 = split_tf32(v.y);
            float2 s2 = split_tf32(v.z), s3 = split_tf32(v.w);
            *(float4*)&Bs2[kk][bn4]     = make_float4(s0.x, s0.y, s1.x, s1.y);
            *(float4*)&Bs2[kk][bn4 + 2] = make_float4(s2.x, s2.y, s3.x, s3.y);
        }
        __syncthreads();

#pragma unroll
        for (int ks = 0; ks < 2; ks++) {
            const int kb = ks * 8;
            float2 a2[4][4];
#pragma unroll
            for (int mi = 0; mi < 4; mi++) {
                int m = wm + mi * 16 + r;
                a2[mi][0] = As2[kb + q][m];
                a2[mi][1] = As2[kb + q][m + 8];
                a2[mi][2] = As2[kb + q + 4][m];
                a2[mi][3] = As2[kb + q + 4][m + 8];
            }
            float2 b2[4][2];
#pragma unroll
            for (int ni = 0; ni < 4; ni++) {
                int n = wn + ni * 8 + r;
                b2[ni][0] = Bs2[kb + q][n];
                b2[ni][1] = Bs2[kb + q + 4][n];
            }
            // pass 1: hi*hi
#pragma unroll
            for (int mi = 0; mi < 4; mi++)
#pragma unroll
                for (int ni = 0; ni < 4; ni++)
                    mma_tf32(acc[mi][ni],
                             a2[mi][0].x, a2[mi][1].x, a2[mi][2].x, a2[mi][3].x,
                             b2[ni][0].x, b2[ni][1].x);
            // pass 2: hi*lo
#pragma unroll
            for (int mi = 0; mi < 4; mi++)
#pragma unroll
                for (int ni = 0; ni < 4; ni++)
                    mma_tf32(acc[mi][ni],
                             a2[mi][0].x, a2[mi][1].x, a2[mi][2].x, a2[mi][3].x,
                             b2[ni][0].y, b2[ni][1].y);
            // pass 3: lo*hi
#pragma unroll
            for (int mi = 0; mi < 4; mi++)
#pragma unroll
                for (int ni = 0; ni < 4; ni++)
                    mma_tf32(acc[mi][ni],
                             a2[mi][0].y, a2[mi][1].y, a2[mi][2].y, a2[mi][3].y,
                             b2[ni][0].x, b2[ni][1].x);
        }
        __syncthreads();
    }

#pragma unroll
    for (int mi = 0; mi < 4; mi++) {
#pragma unroll
        for (int ni = 0; ni < 4; ni++) {
            int row = row0 + wm + mi * 16 + r;
            int c   = col0 + wn + ni * 8 + 2 * q;
            if (c < Nn) {
                float b0 = bias[c], b1 = bias[c + 1];
                float2 v0 = make_float2(acc[mi][ni][0] + b0, acc[mi][ni][1] + b1);
                float2 v1 = make_float2(acc[mi][ni][2] + b0, acc[mi][ni][3] + b1);
                *(float2*)&Cm[(size_t)row * Nn + c]       = v0;
                *(float2*)&Cm[(size_t)(row + 8) * Nn + c] = v1;
            }
        }
    }
}

// ---------------------------------------------------------------------------
// Sampling: warp <-> (b, n, head). Lane group g = lane>>3 owns bilinear
// corner g; each lane loads float4 (8 lanes x 16B = one 128B corner line).
// Corner weight (x attn, x valid) multiplies the load; bfly reduction across
// the 4 corner groups at the end.
// ---------------------------------------------------------------------------
__global__ void sample_kernel(const float* __restrict__ refp) {
    int gw   = (blockIdx.x * blockDim.x + threadIdx.x) >> 5;
    int lane = threadIdx.x & 31;
    if (gw >= B_ * N_ * NH_) return;
    int h  = gw & 7;
    int bn = gw >> 3;
    int b  = bn >> 13;

    int g  = lane >> 3;
    int gx = g & 1, gy = g >> 1;
    int d4 = (lane & 7) * 4;

    const float* pr = g_params + (size_t)bn * P96;

    float rx = refp[2 * bn], ry = refp[2 * bn + 1];
    float bx = 2.f * rx;
    float by = 2.f * ry;

    const float* al = pr + 64 + h * 4;
    float l0 = al[0], l1 = al[1], l2 = al[2], l3 = al[3];
    float mx = fmaxf(fmaxf(l0, l1), fmaxf(l2, l3));
    float e0 = __expf(l0 - mx), e1 = __expf(l1 - mx);
    float e2 = __expf(l2 - mx), e3 = __expf(l3 - mx);
    float inv = 1.f / (e0 + e1 + e2 + e3);
    float aw[4] = {e0 * inv, e1 * inv, e2 * inv, e3 * inv};

    const float* vb = g_valt + (size_t)(b * NH_ + h) * HW_ * D_;

    float4 acc = make_float4(0.f, 0.f, 0.f, 0.f);
#pragma unroll
    for (int p = 0; p < 4; p++) {
        float ox = pr[(h * 4 + p) * 2];
        float oy = pr[(h * 4 + p) * 2 + 1];
        float x = fmaf(bx + ox, (float)W_ * 0.5f, -0.5f);
        float y = fmaf(by + oy, (float)H_ * 0.5f, -0.5f);
        float x0f = floorf(x), y0f = floorf(y);
        float wx = x - x0f, wy = y - y0f;
        int xc = (int)x0f + gx;
        int yc = (int)y0f + gy;
        float wcx = gx ? wx : 1.f - wx;
        float wcy = gy ? wy : 1.f - wy;
        bool valid = (xc >= 0) & (xc < W_) & (yc >= 0) & (yc < H_);
        float wc = valid ? (wcx * wcy * aw[p]) : 0.f;
        int idx = valid ? (yc * W_ + xc) : 0;
        float4 v = *(const float4*)&vb[(size_t)idx * D_ + d4];
        acc.x = fmaf(wc, v.x, acc.x);
        acc.y = fmaf(wc, v.y, acc.y);
        acc.z = fmaf(wc, v.z, acc.z);
        acc.w = fmaf(wc, v.w, acc.w);
    }

#pragma unroll
    for (int off = 8; off <= 16; off <<= 1) {
        acc.x += __shfl_xor_sync(0xffffffffu, acc.x, off);
        acc.y += __shfl_xor_sync(0xffffffffu, acc.y, off);
        acc.z += __shfl_xor_sync(0xffffffffu, acc.z, off);
        acc.w += __shfl_xor_sync(0xffffffffu, acc.w, off);
    }

    if (g == 0)
        *(float4*)&g_agg[(size_t)bn * C_ + h * D_ + d4] = acc;
}

// ---------------------------------------------------------------------------
extern "C" void kernel_launch(void* const* d_in, const int* in_sizes, int n_in,
                              void* d_out, int out_size) {
    const float* query  = (const float*)d_in[0];
    const float* refp   = (const float*)d_in[1];
    const float* value  = (const float*)d_in[2];
    const float* W_off  = (const float*)d_in[3];
    const float* b_off  = (const float*)d_in[4];
    const float* W_attn = (const float*)d_in[5];
    const float* b_attn = (const float*)d_in[6];
    const float* W_out  = (const float*)d_in[7];
    const float* b_out  = (const float*)d_in[8];
    float* out = (float*)d_out;

    float* d_params; cudaGetSymbolAddress((void**)&d_params, g_params);
    float* d_agg;    cudaGetSymbolAddress((void**)&d_agg, g_agg);
    float* d_wcat;   cudaGetSymbolAddress((void**)&d_wcat, g_wcat);
    float* d_bcat;   cudaGetSymbolAddress((void**)&d_bcat, g_bcat);

    concat_w_kernel<<<(C_ * P96 + 255) / 256, 256>>>(W_off, b_off, W_attn, b_attn);
    transpose_val_kernel<<<dim3(HW_ / 32, B_ * NH_), dim3(32, 8)>>>(value);
    tf32x3_gemm_kernel<<<dim3(1, M_ / 128), 256>>>(query, d_wcat, d_bcat, d_params, P96);
    sample_kernel<<<(B_ * N_ * NH_ * 32) / 256, 256>>>(refp);
    tf32x3_gemm_kernel<<<dim3(C_ / 128, M_ / 128), 256>>>(d_agg, W_out, b_out, out, C_);
}

// round 7
// speedup vs baseline: 1.1970x; 1.1970x over previous
#include <cuda_runtime.h>
#include <cuda_fp16.h>
#include <math.h>
#include <stdint.h>

#define B_   8
#define N_   8192
#define C_   256
#define H_   128
#define W_   128
#define NH_  8
#define HW_  (H_ * W_)
#define M_   (B_ * N_)      // 65536
#define P96  96
#define KS   512            // stored K (hi | lo), both GEMMs
#define NKCH 12             // 12 x 64 = K 768 effective (3 sections x 256)

// ---- scratch (static device allocations; no cudaMalloc anywhere) ----
__device__ float g_valt[(size_t)B_ * NH_ * HW_ * 32];       // (B,Hh,HW,D)
__device__ float g_params[(size_t)M_ * P96];                // [off(64) | attn(32)]
__device__ __half g_qs[(size_t)M_ * KS];                    // query splits [M][512]
__device__ __half g_as[(size_t)M_ * KS];                    // agg splits   [M][512]
__device__ __half g_wc[128 * KS];                           // wcat^T splits (pad rows 96-127)
__device__ __half g_wo[C_ * KS];                            // W_out^T splits
__device__ float g_bcat[P96];

// ============================ PTX helpers ==================================
__device__ __forceinline__ uint32_t smem_u32(const void* p) {
    uint32_t a;
    asm("{ .reg .u64 t; cvta.to.shared.u64 t, %1; cvt.u32.u64 %0, t; }"
        : "=r"(a) : "l"(p));
    return a;
}
__device__ __forceinline__ void cp16(uint32_t dst, const void* src) {
    asm volatile("cp.async.cg.shared.global [%0], [%1], 16;" :: "r"(dst), "l"(src));
}
#define CP_COMMIT() asm volatile("cp.async.commit_group;" ::: "memory")
#define CP_WAIT(n)  asm volatile("cp.async.wait_group %0;" :: "n"(n) : "memory")

__device__ __forceinline__ void ldsm4(uint32_t* r, uint32_t addr) {
    asm volatile("ldmatrix.sync.aligned.m8n8.x4.shared.b16 {%0,%1,%2,%3}, [%4];"
                 : "=r"(r[0]), "=r"(r[1]), "=r"(r[2]), "=r"(r[3]) : "r"(addr));
}
__device__ __forceinline__ void mma_f16(float* d, const uint32_t* a, const uint32_t* b) {
    asm volatile(
        "mma.sync.aligned.m16n8k16.row.col.f32.f16.f16.f32 "
        "{%0,%1,%2,%3}, {%4,%5,%6,%7}, {%8,%9}, {%0,%1,%2,%3};"
        : "+f"(d[0]), "+f"(d[1]), "+f"(d[2]), "+f"(d[3])
        : "r"(a[0]), "r"(a[1]), "r"(a[2]), "r"(a[3]), "r"(b[0]), "r"(b[1]));
}
__device__ __forceinline__ uint32_t swz(uint32_t off) { return off ^ ((off >> 3) & 0x70); }

// ============================ fp16 2-way split =============================
__device__ __forceinline__ void split2h(float v, __half& h, __half& l) {
    h = __float2half(v);
    l = __float2half(v - __half2float(h));
}

// query -> [M][512] (hi | lo)
__global__ void split_query_kernel(const float* __restrict__ q) {
    size_t i = (size_t)(blockIdx.x * blockDim.x + threadIdx.x) * 4;
    float4 v = *(const float4*)&q[i];
    size_t row = i >> 8;
    int col = (int)(i & 255);
    __half h[4], l[4];
    split2h(v.x, h[0], l[0]); split2h(v.y, h[1], l[1]);
    split2h(v.z, h[2], l[2]); split2h(v.w, h[3], l[3]);
    __half* base = g_qs + row * KS + col;
    *(__half2*)(base)       = __half2(h[0], h[1]);
    *(__half2*)(base + 2)   = __half2(h[2], h[3]);
    *(__half2*)(base + 256) = __half2(l[0], l[1]);
    *(__half2*)(base + 258) = __half2(l[2], l[3]);
}

// wcat^T -> [128][512] padded with zero rows 96..127
__global__ void prep_wcat_kernel(const float* __restrict__ W_off,
                                 const float* __restrict__ b_off,
                                 const float* __restrict__ W_attn,
                                 const float* __restrict__ b_attn) {
    int id = blockIdx.x * blockDim.x + threadIdx.x;   // 128*256
    int j = id >> 8, k = id & 255;
    float v = 0.f;
    if (j < 64)       v = W_off[k * 64 + j];
    else if (j < 96)  v = W_attn[k * 32 + (j - 64)];
    __half h, l;
    split2h(v, h, l);
    g_wc[j * KS + k] = h; g_wc[j * KS + 256 + k] = l;
    if (id < P96) g_bcat[id] = (id < 64) ? b_off[id] : b_attn[id - 64];
}

// W_out^T -> [256][512]
__global__ void prep_wout_kernel(const float* __restrict__ W_out) {
    int id = blockIdx.x * blockDim.x + threadIdx.x;   // 256*256
    int n = id >> 8, k = id & 255;
    __half h, l;
    split2h(W_out[k * C_ + n], h, l);
    g_wo[n * KS + k] = h; g_wo[n * KS + 256 + k] = l;
}

// ---------------------------------------------------------------------------
// Transpose value (B, Hh*D, H*W) -> (B, Hh, H*W, D)
// ---------------------------------------------------------------------------
__global__ void transpose_val_kernel(const float* __restrict__ val) {
    __shared__ float t[32][33];
    int bh = blockIdx.y;
    int p0 = blockIdx.x * 32;
    const float* src = val + ((size_t)bh * 32) * HW_ + p0;
    for (int d = threadIdx.y; d < 32; d += 8)
        t[d][threadIdx.x] = src[(size_t)d * HW_ + threadIdx.x];
    __syncthreads();
    float* dst = g_valt + (size_t)bh * HW_ * 32 + (size_t)p0 * 32;
    for (int dp = threadIdx.y; dp < 32; dp += 8)
        dst[(size_t)dp * 32 + threadIdx.x] = t[threadIdx.x][dp];
}

// ===========================================================================
// fp16 mma.sync GEMM with error-compensated split products.
//   C = A_hi@B_hi^T + A_hi@B_lo^T + A_lo@B_hi^T  (+bias)
// realized as one K=768 GEMM: section s of 256 pairs A sec Asec[s] with
// B sec Bsec[s], Asec={0,0,1}, Bsec={0,1,0}. Splits stored once ([*][512]).
// 128x128 CTA tile, 8 warps (2x4), warp tile 64x32, m16n8k16.
// cp.async double-buffered 64-wide chunks; SW128-swizzled smem (128B rows);
// ldmatrix.x4 fragment loads.
// ===========================================================================
template <int NSTORE, int LDC>
__global__ __launch_bounds__(256, 2)
void f16_gemm(const __half* __restrict__ A,
              const __half* __restrict__ BT,
              const float* __restrict__ bias,
              float* __restrict__ Cm) {
    extern __shared__ char dyn_raw[];
    const uint32_t raw = smem_u32(dyn_raw);
    const uint32_t sb  = (raw + 1023) & ~1023u;

    const int tid  = threadIdx.x;
    const int wid  = tid >> 5;
    const int lane = tid & 31;
    const int row0 = blockIdx.y * 128;
    const int col0 = blockIdx.x * 128;
    const int wm   = (wid >> 2) * 64;
    const int wn   = (wid & 3) * 32;

    float acc[4][4][4];
#pragma unroll
    for (int mi = 0; mi < 4; mi++)
#pragma unroll
        for (int ni = 0; ni < 4; ni++)
#pragma unroll
            for (int v = 0; v < 4; v++) acc[mi][ni][v] = 0.f;

    const int lrow = tid >> 3;          // 0..31 (x4 rows per iter)
    const int lblk = tid & 7;           // 16B chunk

    // section maps: chunk c -> global k offsets in the [*][512] split arrays
    auto kA = [](int c) { const int s[3] = {0, 0, 256}; return s[c >> 2] + (c & 3) * 64; };
    auto kB = [](int c) { const int s[3] = {0, 256, 0}; return s[c >> 2] + (c & 3) * 64; };

    auto load_stage = [&](int c, int st) {
        uint32_t a_t = sb + st * 32768;
        uint32_t b_t = a_t + 16384;
        const __half* ag = A  + (size_t)(row0 + lrow) * KS + kA(c) + lblk * 8;
        const __half* bg = BT + (size_t)(col0 + lrow) * KS + kB(c) + lblk * 8;
#pragma unroll
        for (int i = 0; i < 4; i++) {
            int r = lrow + i * 32;
            cp16(a_t + swz(r * 128 + lblk * 16), ag + (size_t)i * 32 * KS);
            cp16(b_t + swz(r * 128 + lblk * 16), bg + (size_t)i * 32 * KS);
        }
        CP_COMMIT();
    };

    load_stage(0, 0);

    for (int c = 0; c < NKCH; c++) {
        if (c + 1 < NKCH) { load_stage(c + 1, (c + 1) & 1); CP_WAIT(1); }
        else             { CP_WAIT(0); }
        __syncthreads();

        const uint32_t a_t = sb + (c & 1) * 32768;
        const uint32_t b_t = a_t + 16384;
#pragma unroll
        for (int ks = 0; ks < 4; ks++) {
            uint32_t af[4][4];
#pragma unroll
            for (int mi = 0; mi < 4; mi++) {
                int r  = wm + mi * 16 + (lane & 15);
                int kc = ks * 16 + (lane >> 4) * 8;
                ldsm4(af[mi], a_t + swz(r * 128 + kc * 2));
            }
            uint32_t bf[4][2];
#pragma unroll
            for (int nj = 0; nj < 2; nj++) {
                int gsel = lane >> 3;
                int nrow = wn + (nj * 2 + (gsel >> 1)) * 8 + (lane & 7);
                int kc   = ks * 16 + (gsel & 1) * 8;
                uint32_t r4[4];
                ldsm4(r4, b_t + swz(nrow * 128 + kc * 2));
                bf[nj * 2][0]     = r4[0];
                bf[nj * 2][1]     = r4[1];
                bf[nj * 2 + 1][0] = r4[2];
                bf[nj * 2 + 1][1] = r4[3];
            }
#pragma unroll
            for (int mi = 0; mi < 4; mi++)
#pragma unroll
                for (int ni = 0; ni < 4; ni++)
                    mma_f16(acc[mi][ni], af[mi], bf[ni]);
        }
        __syncthreads();
    }

    // ---- epilogue (guard against FULL width NSTORE; c is absolute) ----
    const int r = lane >> 2;
    const int q = lane & 3;
#pragma unroll
    for (int mi = 0; mi < 4; mi++) {
#pragma unroll
        for (int ni = 0; ni < 4; ni++) {
            int row = row0 + wm + mi * 16 + r;
            int c   = col0 + wn + ni * 8 + 2 * q;
            if (c < NSTORE) {
                float b0 = bias[c], b1 = bias[c + 1];
                float2 v0 = make_float2(acc[mi][ni][0] + b0, acc[mi][ni][1] + b1);
                float2 v1 = make_float2(acc[mi][ni][2] + b0, acc[mi][ni][3] + b1);
                *(float2*)&Cm[(size_t)row * LDC + c]       = v0;
                *(float2*)&Cm[(size_t)(row + 8) * LDC + c] = v1;
            }
        }
    }
}

// ---------------------------------------------------------------------------
// Sampling: warp <-> (b, n, head). Lane group g = lane>>3 owns bilinear
// corner g; each lane loads float4; bfly reduction; writes fp16 2-way split
// of agg into [M][512] (hi | lo).
// ---------------------------------------------------------------------------
__global__ void sample_kernel(const float* __restrict__ refp) {
    int gw   = (blockIdx.x * blockDim.x + threadIdx.x) >> 5;
    int lane = threadIdx.x & 31;
    if (gw >= B_ * N_ * NH_) return;
    int h  = gw & 7;
    int bn = gw >> 3;
    int b  = bn >> 13;

    int g  = lane >> 3;
    int gx = g & 1, gy = g >> 1;
    int d4 = (lane & 7) * 4;

    const float* pr = g_params + (size_t)bn * P96;

    float rx = refp[2 * bn], ry = refp[2 * bn + 1];
    float bx = 2.f * rx;
    float by = 2.f * ry;

    const float* al = pr + 64 + h * 4;
    float l0 = al[0], l1 = al[1], l2 = al[2], l3 = al[3];
    float mx = fmaxf(fmaxf(l0, l1), fmaxf(l2, l3));
    float e0 = __expf(l0 - mx), e1 = __expf(l1 - mx);
    float e2 = __expf(l2 - mx), e3 = __expf(l3 - mx);
    float inv = 1.f / (e0 + e1 + e2 + e3);
    float aw[4] = {e0 * inv, e1 * inv, e2 * inv, e3 * inv};

    const float* vb = g_valt + (size_t)(b * NH_ + h) * HW_ * 32;

    float4 acc = make_float4(0.f, 0.f, 0.f, 0.f);
#pragma unroll
    for (int p = 0; p < 4; p++) {
        float ox = pr[(h * 4 + p) * 2];
        float oy = pr[(h * 4 + p) * 2 + 1];
        float x = fmaf(bx + ox, (float)W_ * 0.5f, -0.5f);
        float y = fmaf(by + oy, (float)H_ * 0.5f, -0.5f);
        float x0f = floorf(x), y0f = floorf(y);
        float wx = x - x0f, wy = y - y0f;
        int xc = (int)x0f + gx;
        int yc = (int)y0f + gy;
        float wcx = gx ? wx : 1.f - wx;
        float wcy = gy ? wy : 1.f - wy;
        bool valid = (xc >= 0) & (xc < W_) & (yc >= 0) & (yc < H_);
        float wc = valid ? (wcx * wcy * aw[p]) : 0.f;
        int idx = valid ? (yc * W_ + xc) : 0;
        float4 v = *(const float4*)&vb[(size_t)idx * 32 + d4];
        acc.x = fmaf(wc, v.x, acc.x);
        acc.y = fmaf(wc, v.y, acc.y);
        acc.z = fmaf(wc, v.z, acc.z);
        acc.w = fmaf(wc, v.w, acc.w);
    }

#pragma unroll
    for (int off = 8; off <= 16; off <<= 1) {
        acc.x += __shfl_xor_sync(0xffffffffu, acc.x, off);
        acc.y += __shfl_xor_sync(0xffffffffu, acc.y, off);
        acc.z += __shfl_xor_sync(0xffffffffu, acc.z, off);
        acc.w += __shfl_xor_sync(0xffffffffu, acc.w, off);
    }

    if (g == 0) {
        __half h0, h1, h2, h3, q0, q1, q2, q3;
        split2h(acc.x, h0, q0); split2h(acc.y, h1, q1);
        split2h(acc.z, h2, q2); split2h(acc.w, h3, q3);
        __half* base = g_as + (size_t)bn * KS + h * 32 + d4;
        *(__half2*)(base)       = __half2(h0, h1);
        *(__half2*)(base + 2)   = __half2(h2, h3);
        *(__half2*)(base + 256) = __half2(q0, q1);
        *(__half2*)(base + 258) = __half2(q2, q3);
    }
}

// ---------------------------------------------------------------------------
extern "C" void kernel_launch(void* const* d_in, const int* in_sizes, int n_in,
                              void* d_out, int out_size) {
    const float* query  = (const float*)d_in[0];
    const float* refp   = (const float*)d_in[1];
    const float* value  = (const float*)d_in[2];
    const float* W_off  = (const float*)d_in[3];
    const float* b_off  = (const float*)d_in[4];
    const float* W_attn = (const float*)d_in[5];
    const float* b_attn = (const float*)d_in[6];
    const float* W_out  = (const float*)d_in[7];
    const float* b_out  = (const float*)d_in[8];
    float* out = (float*)d_out;

    __half *qs, *as, *wc, *wo;
    float *params, *bcat;
    cudaGetSymbolAddress((void**)&qs, g_qs);
    cudaGetSymbolAddress((void**)&as, g_as);
    cudaGetSymbolAddress((void**)&wc, g_wc);
    cudaGetSymbolAddress((void**)&wo, g_wo);
    cudaGetSymbolAddress((void**)&params, g_params);
    cudaGetSymbolAddress((void**)&bcat, g_bcat);

    const int SMEM = 2 * 32768 + 1024;
    cudaFuncSetAttribute(f16_gemm<P96, P96>,
                         cudaFuncAttributeMaxDynamicSharedMemorySize, SMEM);
    cudaFuncSetAttribute(f16_gemm<C_, C_>,
                         cudaFuncAttributeMaxDynamicSharedMemorySize, SMEM);

    split_query_kernel<<<M_ * C_ / 4 / 256, 256>>>(query);
    prep_wcat_kernel<<<128 * C_ / 256, 256>>>(W_off, b_off, W_attn, b_attn);
    prep_wout_kernel<<<C_ * C_ / 256, 256>>>(W_out);
    transpose_val_kernel<<<dim3(HW_ / 32, B_ * NH_), dim3(32, 8)>>>(value);

    // GEMM-1: params[M,96] = q_hi@w_hi + q_hi@w_lo + q_lo@w_hi + bcat
    f16_gemm<P96, P96><<<dim3(1, M_ / 128), 256, SMEM>>>(qs, wc, bcat, params);

    sample_kernel<<<(B_ * N_ * NH_ * 32) / 256, 256>>>(refp);

    // GEMM-2: out[M,256] = a_hi@wo_hi + a_hi@wo_lo + a_lo@wo_hi + b_out
    f16_gemm<C_, C_><<<dim3(2, M_ / 128), 256, SMEM>>>(as, wo, b_out, out);
}

// round 9
// speedup vs baseline: 1.9224x; 1.6061x over previous
#include <cuda_runtime.h>
#include <cuda_fp16.h>
#include <math.h>
#include <stdint.h>

#define B_   8
#define N_   8192
#define C_   256
#define H_   128
#define W_   128
#define NH_  8
#define HW_  (H_ * W_)
#define M_   (B_ * N_)      // 65536
#define P96  96
#define KS   512            // stored K (hi | lo), both GEMMs
#define NKCH 12             // 12 x 64 = K 768 effective (3 sections x 256)

// ---- scratch (static device allocations; no cudaMalloc anywhere) ----
__device__ float g_valt[(size_t)B_ * NH_ * HW_ * 32];       // (B,Hh,HW,D)
__device__ float g_params[(size_t)M_ * P96];                // [off(64) | attn(32)]
__device__ __half g_qs[(size_t)M_ * KS];                    // query splits [M][512]
__device__ __half g_as[(size_t)M_ * KS];                    // agg splits   [M][512]
__device__ __half g_wc[128 * KS];                           // wcat^T splits (pad rows 96-127)
__device__ __half g_wo[C_ * KS];                            // W_out^T splits
__device__ float g_bcat[P96];

// ============================ PTX helpers ==================================
__device__ __forceinline__ uint32_t smem_u32(const void* p) {
    uint32_t a;
    asm("{ .reg .u64 t; cvta.to.shared.u64 t, %1; cvt.u32.u64 %0, t; }"
        : "=r"(a) : "l"(p));
    return a;
}
__device__ __forceinline__ void cp16(uint32_t dst, const void* src) {
    asm volatile("cp.async.cg.shared.global [%0], [%1], 16;" :: "r"(dst), "l"(src));
}
#define CP_COMMIT() asm volatile("cp.async.commit_group;" ::: "memory")
#define CP_WAIT(n)  asm volatile("cp.async.wait_group %0;" :: "n"(n) : "memory")

__device__ __forceinline__ void ldsm4(uint32_t* r, uint32_t addr) {
    asm volatile("ldmatrix.sync.aligned.m8n8.x4.shared.b16 {%0,%1,%2,%3}, [%4];"
                 : "=r"(r[0]), "=r"(r[1]), "=r"(r[2]), "=r"(r[3]) : "r"(addr));
}
__device__ __forceinline__ void mma_f16(float* d, const uint32_t* a, const uint32_t* b) {
    asm volatile(
        "mma.sync.aligned.m16n8k16.row.col.f32.f16.f16.f32 "
        "{%0,%1,%2,%3}, {%4,%5,%6,%7}, {%8,%9}, {%0,%1,%2,%3};"
        : "+f"(d[0]), "+f"(d[1]), "+f"(d[2]), "+f"(d[3])
        : "r"(a[0]), "r"(a[1]), "r"(a[2]), "r"(a[3]), "r"(b[0]), "r"(b[1]));
}
__device__ __forceinline__ uint32_t swz(uint32_t off) { return off ^ ((off >> 3) & 0x70); }

// ============================ fp16 2-way split =============================
__device__ __forceinline__ void split2h(float v, __half& h, __half& l) {
    h = __float2half(v);
    l = __float2half(v - __half2float(h));
}

// query -> [M][512] (hi | lo)
__global__ void split_query_kernel(const float* __restrict__ q) {
    size_t i = (size_t)(blockIdx.x * blockDim.x + threadIdx.x) * 4;
    float4 v = *(const float4*)&q[i];
    size_t row = i >> 8;
    int col = (int)(i & 255);
    __half h[4], l[4];
    split2h(v.x, h[0], l[0]); split2h(v.y, h[1], l[1]);
    split2h(v.z, h[2], l[2]); split2h(v.w, h[3], l[3]);
    __half* base = g_qs + row * KS + col;
    *(__half2*)(base)       = __half2(h[0], h[1]);
    *(__half2*)(base + 2)   = __half2(h[2], h[3]);
    *(__half2*)(base + 256) = __half2(l[0], l[1]);
    *(__half2*)(base + 258) = __half2(l[2], l[3]);
}

// wcat^T -> [128][512] padded with zero rows 96..127
__global__ void prep_wcat_kernel(const float* __restrict__ W_off,
                                 const float* __restrict__ b_off,
                                 const float* __restrict__ W_attn,
                                 const float* __restrict__ b_attn) {
    int id = blockIdx.x * blockDim.x + threadIdx.x;   // 128*256
    int j = id >> 8, k = id & 255;
    float v = 0.f;
    if (j < 64)       v = W_off[k * 64 + j];
    else if (j < 96)  v = W_attn[k * 32 + (j - 64)];
    __half h, l;
    split2h(v, h, l);
    g_wc[j * KS + k] = h; g_wc[j * KS + 256 + k] = l;
    if (id < P96) g_bcat[id] = (id < 64) ? b_off[id] : b_attn[id - 64];
}

// W_out^T -> [256][512]
__global__ void prep_wout_kernel(const float* __restrict__ W_out) {
    int id = blockIdx.x * blockDim.x + threadIdx.x;   // 256*256
    int n = id >> 8, k = id & 255;
    __half h, l;
    split2h(W_out[k * C_ + n], h, l);
    g_wo[n * KS + k] = h; g_wo[n * KS + 256 + k] = l;
}

// ---------------------------------------------------------------------------
// Transpose v3: (B, Hh*D, H*W) -> (B, Hh, H*W, D).
// 64-position x 32-channel tiles, smem as float4 t4[64][8] with XOR block
// swizzle (dq ^ (p&7)): 16B-aligned everywhere (no pad), conflict-free in
// both phases (each 8-lane phase spans 8 distinct 16B blocks). Loads 128B-
// coalesced per warp; stores 128B per quarter-warp STG.128.
// ---------------------------------------------------------------------------
__global__ void transpose_val_kernel(const float* __restrict__ val) {
    __shared__ float4 t4[64][8];
    int bh = blockIdx.y;
    int p0 = blockIdx.x * 64;
    int tid = threadIdx.x;
    int dl = tid >> 6;         // 0..3
    int pl = tid & 63;         // 0..63
    const float* src = val + ((size_t)bh * 32) * HW_ + p0 + pl;
#pragma unroll
    for (int i = 0; i < 2; i++) {
        int dq = dl * 2 + i;   // 0..7
        float4 v;
        v.x = src[(size_t)(dq * 4 + 0) * HW_];
        v.y = src[(size_t)(dq * 4 + 1) * HW_];
        v.z = src[(size_t)(dq * 4 + 2) * HW_];
        v.w = src[(size_t)(dq * 4 + 3) * HW_];
        t4[pl][dq ^ (pl & 7)] = v;
    }
    __syncthreads();
    int c  = tid & 7;          // output d-quad
    int pw = tid >> 3;         // 0..31
    float* dst = g_valt + (size_t)bh * HW_ * 32 + (size_t)p0 * 32;
#pragma unroll
    for (int i = 0; i < 2; i++) {
        int p = pw + i * 32;
        *(float4*)&dst[(size_t)p * 32 + c * 4] = t4[p][c ^ (p & 7)];
    }
}

// ===========================================================================
// fp16 mma.sync GEMM with error-compensated split products.
//   C = A_hi@B_hi^T + A_hi@B_lo^T + A_lo@B_hi^T  (+bias)
// One K=768 GEMM: chunk c (64-wide) reads A section {hi,hi,lo}[c/4],
// B section {hi,lo,hi}[c/4]. 128x128 CTA tile, 8 warps, warp tile 64x32,
// m16n8k16. 3-stage cp.async pipeline, ONE __syncthreads per chunk:
//   wait(c) -> sync -> issue(c+2) -> compute(c).
// ===========================================================================
template <int NSTORE, int LDC>
__global__ __launch_bounds__(256, 2)
void f16_gemm(const __half* __restrict__ A,
              const __half* __restrict__ BT,
              const float* __restrict__ bias,
              float* __restrict__ Cm) {
    extern __shared__ char dyn_raw[];
    const uint32_t raw = smem_u32(dyn_raw);
    const uint32_t sb  = (raw + 1023) & ~1023u;

    const int tid  = threadIdx.x;
    const int wid  = tid >> 5;
    const int lane = tid & 31;
    const int row0 = blockIdx.y * 128;
    const int col0 = blockIdx.x * 128;
    const int wm   = (wid >> 2) * 64;
    const int wn   = (wid & 3) * 32;

    float acc[4][4][4];
#pragma unroll
    for (int mi = 0; mi < 4; mi++)
#pragma unroll
        for (int ni = 0; ni < 4; ni++)
#pragma unroll
            for (int v = 0; v < 4; v++) acc[mi][ni][v] = 0.f;

    const int lrow = tid >> 3;          // 0..31 (x4 rows per iter)
    const int lblk = tid & 7;           // 16B chunk

    // section maps: chunk c -> global k offsets in the [*][512] split arrays
    auto kA = [](int c) { const int s[3] = {0, 0, 256}; return s[c >> 2] + (c & 3) * 64; };
    auto kB = [](int c) { const int s[3] = {0, 256, 0}; return s[c >> 2] + (c & 3) * 64; };

    auto load_stage = [&](int c, int st) {
        uint32_t a_t = sb + st * 32768;
        uint32_t b_t = a_t + 16384;
        const __half* ag = A  + (size_t)(row0 + lrow) * KS + kA(c) + lblk * 8;
        const __half* bg = BT + (size_t)(col0 + lrow) * KS + kB(c) + lblk * 8;
#pragma unroll
        for (int i = 0; i < 4; i++) {
            int r = lrow + i * 32;
            cp16(a_t + swz(r * 128 + lblk * 16), ag + (size_t)i * 32 * KS);
            cp16(b_t + swz(r * 128 + lblk * 16), bg + (size_t)i * 32 * KS);
        }
        CP_COMMIT();
    };

    load_stage(0, 0);
    load_stage(1, 1);

    for (int c = 0; c < NKCH; c++) {
        if (c + 1 < NKCH) { CP_WAIT(1); } else { CP_WAIT(0); }
        __syncthreads();                 // everyone done reading stage (c-1)%3 too
        if (c + 2 < NKCH) load_stage(c + 2, (c + 2) % 3);

        const uint32_t a_t = sb + (c % 3) * 32768;
        const uint32_t b_t = a_t + 16384;
#pragma unroll
        for (int ks = 0; ks < 4; ks++) {
            uint32_t af[4][4];
#pragma unroll
            for (int mi = 0; mi < 4; mi++) {
                int r  = wm + mi * 16 + (lane & 15);
                int kc = ks * 16 + (lane >> 4) * 8;
                ldsm4(af[mi], a_t + swz(r * 128 + kc * 2));
            }
            uint32_t bf[4][2];
#pragma unroll
            for (int nj = 0; nj < 2; nj++) {
                int gsel = lane >> 3;
                int nrow = wn + (nj * 2 + (gsel >> 1)) * 8 + (lane & 7);
                int kc   = ks * 16 + (gsel & 1) * 8;
                uint32_t r4[4];
                ldsm4(r4, b_t + swz(nrow * 128 + kc * 2));
                bf[nj * 2][0]     = r4[0];
                bf[nj * 2][1]     = r4[1];
                bf[nj * 2 + 1][0] = r4[2];
                bf[nj * 2 + 1][1] = r4[3];
            }
#pragma unroll
            for (int mi = 0; mi < 4; mi++)
#pragma unroll
                for (int ni = 0; ni < 4; ni++)
                    mma_f16(acc[mi][ni], af[mi], bf[ni]);
        }
    }

    // ---- epilogue ----
    const int r = lane >> 2;
    const int q = lane & 3;
#pragma unroll
    for (int mi = 0; mi < 4; mi++) {
#pragma unroll
        for (int ni = 0; ni < 4; ni++) {
            int row = row0 + wm + mi * 16 + r;
            int c   = col0 + wn + ni * 8 + 2 * q;
            if (c < NSTORE) {
                float b0 = bias[c], b1 = bias[c + 1];
                float2 v0 = make_float2(acc[mi][ni][0] + b0, acc[mi][ni][1] + b1);
                float2 v1 = make_float2(acc[mi][ni][2] + b0, acc[mi][ni][3] + b1);
                *(float2*)&Cm[(size_t)row * LDC + c]       = v0;
                *(float2*)&Cm[(size_t)(row + 8) * LDC + c] = v1;
            }
        }
    }
}

// ---------------------------------------------------------------------------
// Sampling: warp <-> (b, n, head). Lane group g = lane>>3 owns bilinear
// corner g; each lane loads float4; bfly reduction; writes fp16 2-way split
// of agg into [M][512] (hi | lo).
// ---------------------------------------------------------------------------
__global__ void sample_kernel(const float* __restrict__ refp) {
    int gw   = (blockIdx.x * blockDim.x + threadIdx.x) >> 5;
    int lane = threadIdx.x & 31;
    if (gw >= B_ * N_ * NH_) return;
    int h  = gw & 7;
    int bn = gw >> 3;
    int b  = bn >> 13;

    int g  = lane >> 3;
    int gx = g & 1, gy = g >> 1;
    int d4 = (lane & 7) * 4;

    const float* pr = g_params + (size_t)bn * P96;

    float rx = refp[2 * bn], ry = refp[2 * bn + 1];
    float bx = 2.f * rx;
    float by = 2.f * ry;

    const float* al = pr + 64 + h * 4;
    float l0 = al[0], l1 = al[1], l2 = al[2], l3 = al[3];
    float mx = fmaxf(fmaxf(l0, l1), fmaxf(l2, l3));
    float e0 = __expf(l0 - mx), e1 = __expf(l1 - mx);
    float e2 = __expf(l2 - mx), e3 = __expf(l3 - mx);
    float inv = 1.f / (e0 + e1 + e2 + e3);
    float aw[4] = {e0 * inv, e1 * inv, e2 * inv, e3 * inv};

    const float* vb = g_valt + (size_t)(b * NH_ + h) * HW_ * 32;

    float4 acc = make_float4(0.f, 0.f, 0.f, 0.f);
#pragma unroll
    for (int p = 0; p < 4; p++) {
        float ox = pr[(h * 4 + p) * 2];
        float oy = pr[(h * 4 + p) * 2 + 1];
        float x = fmaf(bx + ox, (float)W_ * 0.5f, -0.5f);
        float y = fmaf(by + oy, (float)H_ * 0.5f, -0.5f);
        float x0f = floorf(x), y0f = floorf(y);
        float wx = x - x0f, wy = y - y0f;
        int xc = (int)x0f + gx;
        int yc = (int)y0f + gy;
        float wcx = gx ? wx : 1.f - wx;
        float wcy = gy ? wy : 1.f - wy;
        bool valid = (xc >= 0) & (xc < W_) & (yc >= 0) & (yc < H_);
        float wc = valid ? (wcx * wcy * aw[p]) : 0.f;
        int idx = valid ? (yc * W_ + xc) : 0;
        float4 v = *(const float4*)&vb[(size_t)idx * 32 + d4];
        acc.x = fmaf(wc, v.x, acc.x);
        acc.y = fmaf(wc, v.y, acc.y);
        acc.z = fmaf(wc, v.z, acc.z);
        acc.w = fmaf(wc, v.w, acc.w);
    }

#pragma unroll
    for (int off = 8; off <= 16; off <<= 1) {
        acc.x += __shfl_xor_sync(0xffffffffu, acc.x, off);
        acc.y += __shfl_xor_sync(0xffffffffu, acc.y, off);
        acc.z += __shfl_xor_sync(0xffffffffu, acc.z, off);
        acc.w += __shfl_xor_sync(0xffffffffu, acc.w, off);
    }

    if (g == 0) {
        __half h0, h1, h2, h3, q0, q1, q2, q3;
        split2h(acc.x, h0, q0); split2h(acc.y, h1, q1);
        split2h(acc.z, h2, q2); split2h(acc.w, h3, q3);
        __half* base = g_as + (size_t)bn * KS + h * 32 + d4;
        *(__half2*)(base)       = __half2(h0, h1);
        *(__half2*)(base + 2)   = __half2(h2, h3);
        *(__half2*)(base + 256) = __half2(q0, q1);
        *(__half2*)(base + 258) = __half2(q2, q3);
    }
}

// ---------------------------------------------------------------------------
extern "C" void kernel_launch(void* const* d_in, const int* in_sizes, int n_in,
                              void* d_out, int out_size) {
    const float* query  = (const float*)d_in[0];
    const float* refp   = (const float*)d_in[1];
    const float* value  = (const float*)d_in[2];
    const float* W_off  = (const float*)d_in[3];
    const float* b_off  = (const float*)d_in[4];
    const float* W_attn = (const float*)d_in[5];
    const float* b_attn = (const float*)d_in[6];
    const float* W_out  = (const float*)d_in[7];
    const float* b_out  = (const float*)d_in[8];
    float* out = (float*)d_out;

    __half *qs, *as, *wc, *wo;
    float *params, *bcat;
    cudaGetSymbolAddress((void**)&qs, g_qs);
    cudaGetSymbolAddress((void**)&as, g_as);
    cudaGetSymbolAddress((void**)&wc, g_wc);
    cudaGetSymbolAddress((void**)&wo, g_wo);
    cudaGetSymbolAddress((void**)&params, g_params);
    cudaGetSymbolAddress((void**)&bcat, g_bcat);

    const int SMEM = 3 * 32768 + 1024;   // 3-stage pipeline + align pad
    cudaFuncSetAttribute(f16_gemm<P96, P96>,
                         cudaFuncAttributeMaxDynamicSharedMemorySize, SMEM);
    cudaFuncSetAttribute(f16_gemm<C_, C_>,
                         cudaFuncAttributeMaxDynamicSharedMemorySize, SMEM);

    split_query_kernel<<<M_ * C_ / 4 / 256, 256>>>(query);
    prep_wcat_kernel<<<128 * C_ / 256, 256>>>(W_off, b_off, W_attn, b_attn);
    prep_wout_kernel<<<C_ * C_ / 256, 256>>>(W_out);
    transpose_val_kernel<<<dim3(HW_ / 64, B_ * NH_), 256>>>(value);

    // GEMM-1: params[M,96] = q_hi@w_hi + q_hi@w_lo + q_lo@w_hi + bcat
    f16_gemm<P96, P96><<<dim3(1, M_ / 128), 256, SMEM>>>(qs, wc, bcat, params);

    sample_kernel<<<(B_ * N_ * NH_ * 32) / 256, 256>>>(refp);

    // GEMM-2: out[M,256] = a_hi@wo_hi + a_hi@wo_lo + a_lo@wo_hi + b_out
    f16_gemm<C_, C_><<<dim3(2, M_ / 128), 256, SMEM>>>(as, wo, b_out, out);
}

// round 10
// speedup vs baseline: 1.9641x; 1.0216x over previous
#include <cuda_runtime.h>
#include <cuda_fp16.h>
#include <math.h>
#include <stdint.h>

#define B_   8
#define N_   8192
#define C_   256
#define H_   128
#define W_   128
#define NH_  8
#define HW_  (H_ * W_)
#define M_   (B_ * N_)      // 65536
#define P96  96
#define KS   512            // stored K (hi | lo), both GEMMs
#define NKCH 12             // 12 x 64 = K 768 effective (3 sections x 256)

// ---- scratch (static device allocations; no cudaMalloc anywhere) ----
__device__ __half g_valth[(size_t)B_ * NH_ * HW_ * 32];     // (B,Hh,HW,D) fp16, 67MB (L2-resident)
__device__ float g_params[(size_t)M_ * P96];                // [off(64) | attn(32)]
__device__ __half g_qs[(size_t)M_ * KS];                    // query splits [M][512]
__device__ __half g_as[(size_t)M_ * KS];                    // agg splits   [M][512]
__device__ __half g_wc[128 * KS];                           // wcat^T splits (pad rows 96-127)
__device__ __half g_wo[C_ * KS];                            // W_out^T splits
__device__ float g_bcat[P96];

// ============================ PTX helpers ==================================
__device__ __forceinline__ uint32_t smem_u32(const void* p) {
    uint32_t a;
    asm("{ .reg .u64 t; cvta.to.shared.u64 t, %1; cvt.u32.u64 %0, t; }"
        : "=r"(a) : "l"(p));
    return a;
}
__device__ __forceinline__ void cp16(uint32_t dst, const void* src) {
    asm volatile("cp.async.cg.shared.global [%0], [%1], 16;" :: "r"(dst), "l"(src));
}
#define CP_COMMIT() asm volatile("cp.async.commit_group;" ::: "memory")
#define CP_WAIT(n)  asm volatile("cp.async.wait_group %0;" :: "n"(n) : "memory")

__device__ __forceinline__ void ldsm4(uint32_t* r, uint32_t addr) {
    asm volatile("ldmatrix.sync.aligned.m8n8.x4.shared.b16 {%0,%1,%2,%3}, [%4];"
                 : "=r"(r[0]), "=r"(r[1]), "=r"(r[2]), "=r"(r[3]) : "r"(addr));
}
__device__ __forceinline__ void mma_f16(float* d, const uint32_t* a, const uint32_t* b) {
    asm volatile(
        "mma.sync.aligned.m16n8k16.row.col.f32.f16.f16.f32 "
        "{%0,%1,%2,%3}, {%4,%5,%6,%7}, {%8,%9}, {%0,%1,%2,%3};"
        : "+f"(d[0]), "+f"(d[1]), "+f"(d[2]), "+f"(d[3])
        : "r"(a[0]), "r"(a[1]), "r"(a[2]), "r"(a[3]), "r"(b[0]), "r"(b[1]));
}
__device__ __forceinline__ uint32_t swz(uint32_t off) { return off ^ ((off >> 3) & 0x70); }

// ============================ fp16 2-way split =============================
__device__ __forceinline__ void split2h(float v, __half& h, __half& l) {
    h = __float2half(v);
    l = __float2half(v - __half2float(h));
}

// query -> [M][512] (hi | lo)
__global__ void split_query_kernel(const float* __restrict__ q) {
    size_t i = (size_t)(blockIdx.x * blockDim.x + threadIdx.x) * 4;
    float4 v = *(const float4*)&q[i];
    size_t row = i >> 8;
    int col = (int)(i & 255);
    __half h[4], l[4];
    split2h(v.x, h[0], l[0]); split2h(v.y, h[1], l[1]);
    split2h(v.z, h[2], l[2]); split2h(v.w, h[3], l[3]);
    __half* base = g_qs + row * KS + col;
    *(__half2*)(base)       = __half2(h[0], h[1]);
    *(__half2*)(base + 2)   = __half2(h[2], h[3]);
    *(__half2*)(base + 256) = __half2(l[0], l[1]);
    *(__half2*)(base + 258) = __half2(l[2], l[3]);
}

// wcat^T -> [128][512] padded with zero rows 96..127
__global__ void prep_wcat_kernel(const float* __restrict__ W_off,
                                 const float* __restrict__ b_off,
                                 const float* __restrict__ W_attn,
                                 const float* __restrict__ b_attn) {
    int id = blockIdx.x * blockDim.x + threadIdx.x;   // 128*256
    int j = id >> 8, k = id & 255;
    float v = 0.f;
    if (j < 64)       v = W_off[k * 64 + j];
    else if (j < 96)  v = W_attn[k * 32 + (j - 64)];
    __half h, l;
    split2h(v, h, l);
    g_wc[j * KS + k] = h; g_wc[j * KS + 256 + k] = l;
    if (id < P96) g_bcat[id] = (id < 64) ? b_off[id] : b_attn[id - 64];
}

// W_out^T -> [256][512]
__global__ void prep_wout_kernel(const float* __restrict__ W_out) {
    int id = blockIdx.x * blockDim.x + threadIdx.x;   // 256*256
    int n = id >> 8, k = id & 255;
    __half h, l;
    split2h(W_out[k * C_ + n], h, l);
    g_wo[n * KS + k] = h; g_wo[n * KS + 256 + k] = l;
}

// ---------------------------------------------------------------------------
// Transpose v4: (B, Hh*D, H*W) fp32 -> (B, Hh, H*W, D) fp16.
// Same XOR-swizzled float4 staging as v3 (conflict-free, 16B-aligned);
// phase 2 converts to __half and stores 8B per lane (warp = 256B contig).
// ---------------------------------------------------------------------------
__global__ void transpose_val_kernel(const float* __restrict__ val) {
    __shared__ float4 t4[64][8];
    int bh = blockIdx.y;
    int p0 = blockIdx.x * 64;
    int tid = threadIdx.x;
    int dl = tid >> 6;         // 0..3
    int pl = tid & 63;         // 0..63
    const float* src = val + ((size_t)bh * 32) * HW_ + p0 + pl;
#pragma unroll
    for (int i = 0; i < 2; i++) {
        int dq = dl * 2 + i;   // 0..7
        float4 v;
        v.x = src[(size_t)(dq * 4 + 0) * HW_];
        v.y = src[(size_t)(dq * 4 + 1) * HW_];
        v.z = src[(size_t)(dq * 4 + 2) * HW_];
        v.w = src[(size_t)(dq * 4 + 3) * HW_];
        t4[pl][dq ^ (pl & 7)] = v;
    }
    __syncthreads();
    int c  = tid & 7;          // output d-quad
    int pw = tid >> 3;         // 0..31
    __half* dst = g_valth + (size_t)bh * HW_ * 32 + (size_t)p0 * 32;
#pragma unroll
    for (int i = 0; i < 2; i++) {
        int p = pw + i * 32;
        float4 v = t4[p][c ^ (p & 7)];
        __half2 h01 = __floats2half2_rn(v.x, v.y);
        __half2 h23 = __floats2half2_rn(v.z, v.w);
        uint2 u;
        u.x = *reinterpret_cast<uint32_t*>(&h01);
        u.y = *reinterpret_cast<uint32_t*>(&h23);
        *(uint2*)&dst[(size_t)p * 32 + c * 4] = u;
    }
}

// ===========================================================================
// fp16 mma.sync GEMM with error-compensated split products.
//   C = A_hi@B_hi^T + A_hi@B_lo^T + A_lo@B_hi^T  (+bias)
// One K=768 GEMM: chunk c (64-wide) reads A section {hi,hi,lo}[c/4],
// B section {hi,lo,hi}[c/4]. 128x128 CTA tile, 8 warps, warp tile 64x32,
// m16n8k16. 3-stage cp.async pipeline, ONE __syncthreads per chunk:
//   wait(c) -> sync -> issue(c+2) -> compute(c).
// ===========================================================================
template <int NSTORE, int LDC>
__global__ __launch_bounds__(256, 2)
void f16_gemm(const __half* __restrict__ A,
              const __half* __restrict__ BT,
              const float* __restrict__ bias,
              float* __restrict__ Cm) {
    extern __shared__ char dyn_raw[];
    const uint32_t raw = smem_u32(dyn_raw);
    const uint32_t sb  = (raw + 1023) & ~1023u;

    const int tid  = threadIdx.x;
    const int wid  = tid >> 5;
    const int lane = tid & 31;
    const int row0 = blockIdx.y * 128;
    const int col0 = blockIdx.x * 128;
    const int wm   = (wid >> 2) * 64;
    const int wn   = (wid & 3) * 32;

    float acc[4][4][4];
#pragma unroll
    for (int mi = 0; mi < 4; mi++)
#pragma unroll
        for (int ni = 0; ni < 4; ni++)
#pragma unroll
            for (int v = 0; v < 4; v++) acc[mi][ni][v] = 0.f;

    const int lrow = tid >> 3;          // 0..31 (x4 rows per iter)
    const int lblk = tid & 7;           // 16B chunk

    // section maps: chunk c -> global k offsets in the [*][512] split arrays
    auto kA = [](int c) { const int s[3] = {0, 0, 256}; return s[c >> 2] + (c & 3) * 64; };
    auto kB = [](int c) { const int s[3] = {0, 256, 0}; return s[c >> 2] + (c & 3) * 64; };

    auto load_stage = [&](int c, int st) {
        uint32_t a_t = sb + st * 32768;
        uint32_t b_t = a_t + 16384;
        const __half* ag = A  + (size_t)(row0 + lrow) * KS + kA(c) + lblk * 8;
        const __half* bg = BT + (size_t)(col0 + lrow) * KS + kB(c) + lblk * 8;
#pragma unroll
        for (int i = 0; i < 4; i++) {
            int r = lrow + i * 32;
            cp16(a_t + swz(r * 128 + lblk * 16), ag + (size_t)i * 32 * KS);
            cp16(b_t + swz(r * 128 + lblk * 16), bg + (size_t)i * 32 * KS);
        }
        CP_COMMIT();
    };

    load_stage(0, 0);
    load_stage(1, 1);

    for (int c = 0; c < NKCH; c++) {
        if (c + 1 < NKCH) { CP_WAIT(1); } else { CP_WAIT(0); }
        __syncthreads();                 // everyone done reading stage (c-1)%3 too
        if (c + 2 < NKCH) load_stage(c + 2, (c + 2) % 3);

        const uint32_t a_t = sb + (c % 3) * 32768;
        const uint32_t b_t = a_t + 16384;
#pragma unroll
        for (int ks = 0; ks < 4; ks++) {
            uint32_t af[4][4];
#pragma unroll
            for (int mi = 0; mi < 4; mi++) {
                int r  = wm + mi * 16 + (lane & 15);
                int kc = ks * 16 + (lane >> 4) * 8;
                ldsm4(af[mi], a_t + swz(r * 128 + kc * 2));
            }
            uint32_t bf[4][2];
#pragma unroll
            for (int nj = 0; nj < 2; nj++) {
                int gsel = lane >> 3;
                int nrow = wn + (nj * 2 + (gsel >> 1)) * 8 + (lane & 7);
                int kc   = ks * 16 + (gsel & 1) * 8;
                uint32_t r4[4];
                ldsm4(r4, b_t + swz(nrow * 128 + kc * 2));
                bf[nj * 2][0]     = r4[0];
                bf[nj * 2][1]     = r4[1];
                bf[nj * 2 + 1][0] = r4[2];
                bf[nj * 2 + 1][1] = r4[3];
            }
#pragma unroll
            for (int mi = 0; mi < 4; mi++)
#pragma unroll
                for (int ni = 0; ni < 4; ni++)
                    mma_f16(acc[mi][ni], af[mi], bf[ni]);
        }
    }

    // ---- epilogue ----
    const int r = lane >> 2;
    const int q = lane & 3;
#pragma unroll
    for (int mi = 0; mi < 4; mi++) {
#pragma unroll
        for (int ni = 0; ni < 4; ni++) {
            int row = row0 + wm + mi * 16 + r;
            int c   = col0 + wn + ni * 8 + 2 * q;
            if (c < NSTORE) {
                float b0 = bias[c], b1 = bias[c + 1];
                float2 v0 = make_float2(acc[mi][ni][0] + b0, acc[mi][ni][1] + b1);
                float2 v1 = make_float2(acc[mi][ni][2] + b0, acc[mi][ni][3] + b1);
                *(float2*)&Cm[(size_t)row * LDC + c]       = v0;
                *(float2*)&Cm[(size_t)(row + 8) * LDC + c] = v1;
            }
        }
    }
}

// ---------------------------------------------------------------------------
// Sampling: warp <-> (b, n, head). Lane group g = lane>>3 owns bilinear
// corner g; each lane loads 4 fp16 values (uint2, 8B; 8 lanes = full 64B
// corner line); bfly reduction; writes fp16 2-way split of agg to [M][512].
// ---------------------------------------------------------------------------
__global__ void sample_kernel(const float* __restrict__ refp) {
    int gw   = (blockIdx.x * blockDim.x + threadIdx.x) >> 5;
    int lane = threadIdx.x & 31;
    if (gw >= B_ * N_ * NH_) return;
    int h  = gw & 7;
    int bn = gw >> 3;
    int b  = bn >> 13;

    int g  = lane >> 3;
    int gx = g & 1, gy = g >> 1;
    int d4 = (lane & 7) * 4;

    const float* pr = g_params + (size_t)bn * P96;

    float rx = refp[2 * bn], ry = refp[2 * bn + 1];
    float bx = 2.f * rx;
    float by = 2.f * ry;

    const float* al = pr + 64 + h * 4;
    float l0 = al[0], l1 = al[1], l2 = al[2], l3 = al[3];
    float mx = fmaxf(fmaxf(l0, l1), fmaxf(l2, l3));
    float e0 = __expf(l0 - mx), e1 = __expf(l1 - mx);
    float e2 = __expf(l2 - mx), e3 = __expf(l3 - mx);
    float inv = 1.f / (e0 + e1 + e2 + e3);
    float aw[4] = {e0 * inv, e1 * inv, e2 * inv, e3 * inv};

    const __half* vb = g_valth + (size_t)(b * NH_ + h) * HW_ * 32;

    float4 acc = make_float4(0.f, 0.f, 0.f, 0.f);
#pragma unroll
    for (int p = 0; p < 4; p++) {
        float ox = pr[(h * 4 + p) * 2];
        float oy = pr[(h * 4 + p) * 2 + 1];
        float x = fmaf(bx + ox, (float)W_ * 0.5f, -0.5f);
        float y = fmaf(by + oy, (float)H_ * 0.5f, -0.5f);
        float x0f = floorf(x), y0f = floorf(y);
        float wx = x - x0f, wy = y - y0f;
        int xc = (int)x0f + gx;
        int yc = (int)y0f + gy;
        float wcx = gx ? wx : 1.f - wx;
        float wcy = gy ? wy : 1.f - wy;
        bool valid = (xc >= 0) & (xc < W_) & (yc >= 0) & (yc < H_);
        float wc = valid ? (wcx * wcy * aw[p]) : 0.f;
        int idx = valid ? (yc * W_ + xc) : 0;
        uint2 u = *(const uint2*)&vb[(size_t)idx * 32 + d4];
        __half2 h01 = *reinterpret_cast<__half2*>(&u.x);
        __half2 h23 = *reinterpret_cast<__half2*>(&u.y);
        float2 f01 = __half22float2(h01);
        float2 f23 = __half22float2(h23);
        acc.x = fmaf(wc, f01.x, acc.x);
        acc.y = fmaf(wc, f01.y, acc.y);
        acc.z = fmaf(wc, f23.x, acc.z);
        acc.w = fmaf(wc, f23.y, acc.w);
    }

#pragma unroll
    for (int off = 8; off <= 16; off <<= 1) {
        acc.x += __shfl_xor_sync(0xffffffffu, acc.x, off);
        acc.y += __shfl_xor_sync(0xffffffffu, acc.y, off);
        acc.z += __shfl_xor_sync(0xffffffffu, acc.z, off);
        acc.w += __shfl_xor_sync(0xffffffffu, acc.w, off);
    }

    if (g == 0) {
        __half h0, h1, h2, h3, q0, q1, q2, q3;
        split2h(acc.x, h0, q0); split2h(acc.y, h1, q1);
        split2h(acc.z, h2, q2); split2h(acc.w, h3, q3);
        __half* base = g_as + (size_t)bn * KS + h * 32 + d4;
        *(__half2*)(base)       = __half2(h0, h1);
        *(__half2*)(base + 2)   = __half2(h2, h3);
        *(__half2*)(base + 256) = __half2(q0, q1);
        *(__half2*)(base + 258) = __half2(q2, q3);
    }
}

// ---------------------------------------------------------------------------
extern "C" void kernel_launch(void* const* d_in, const int* in_sizes, int n_in,
                              void* d_out, int out_size) {
    const float* query  = (const float*)d_in[0];
    const float* refp   = (const float*)d_in[1];
    const float* value  = (const float*)d_in[2];
    const float* W_off  = (const float*)d_in[3];
    const float* b_off  = (const float*)d_in[4];
    const float* W_attn = (const float*)d_in[5];
    const float* b_attn = (const float*)d_in[6];
    const float* W_out  = (const float*)d_in[7];
    const float* b_out  = (const float*)d_in[8];
    float* out = (float*)d_out;

    __half *qs, *as, *wc, *wo;
    float *params, *bcat;
    cudaGetSymbolAddress((void**)&qs, g_qs);
    cudaGetSymbolAddress((void**)&as, g_as);
    cudaGetSymbolAddress((void**)&wc, g_wc);
    cudaGetSymbolAddress((void**)&wo, g_wo);
    cudaGetSymbolAddress((void**)&params, g_params);
    cudaGetSymbolAddress((void**)&bcat, g_bcat);

    const int SMEM = 3 * 32768 + 1024;   // 3-stage pipeline + align pad
    cudaFuncSetAttribute(f16_gemm<P96, P96>,
                         cudaFuncAttributeMaxDynamicSharedMemorySize, SMEM);
    cudaFuncSetAttribute(f16_gemm<C_, C_>,
                         cudaFuncAttributeMaxDynamicSharedMemorySize, SMEM);

    split_query_kernel<<<M_ * C_ / 4 / 256, 256>>>(query);
    prep_wcat_kernel<<<128 * C_ / 256, 256>>>(W_off, b_off, W_attn, b_attn);
    prep_wout_kernel<<<C_ * C_ / 256, 256>>>(W_out);
    transpose_val_kernel<<<dim3(HW_ / 64, B_ * NH_), 256>>>(value);

    // GEMM-1: params[M,96] = q_hi@w_hi + q_hi@w_lo + q_lo@w_hi + bcat
    f16_gemm<P96, P96><<<dim3(1, M_ / 128), 256, SMEM>>>(qs, wc, bcat, params);

    sample_kernel<<<(B_ * N_ * NH_ * 32) / 256, 256>>>(refp);

    // GEMM-2: out[M,256] = a_hi@wo_hi + a_hi@wo_lo + a_lo@wo_hi + b_out
    f16_gemm<C_, C_><<<dim3(2, M_ / 128), 256, SMEM>>>(as, wo, b_out, out);
}

// round 11
// speedup vs baseline: 2.3473x; 1.1951x over previous
#include <cuda_runtime.h>
#include <cuda_fp16.h>
#include <math.h>
#include <stdint.h>

#define B_   8
#define N_   8192
#define C_   256
#define H_   128
#define W_   128
#define NH_  8
#define HW_  (H_ * W_)
#define M_   (B_ * N_)      // 65536
#define P96  96
#define KS   512            // stored K (hi | lo), both GEMMs
#define NKCH 12             // 12 x 64 = K 768 effective (3 sections x 256)

// ---- scratch (static device allocations; no cudaMalloc anywhere) ----
__device__ __half g_valth[(size_t)B_ * NH_ * HW_ * 32];     // (B,Hh,HW,D) fp16, 67MB (L2-resident)
__device__ float g_params[(size_t)M_ * P96];                // [off(64) | attn(32)]
__device__ __half g_qs[(size_t)M_ * KS];                    // query splits [M][512]
__device__ __half g_as[(size_t)M_ * KS];                    // agg splits   [M][512]
__device__ __half g_wc[128 * KS];                           // wcat^T splits (pad rows 96-127)
__device__ __half g_wo[C_ * KS];                            // W_out^T splits
__device__ float g_bcat[P96];

// ============================ PTX helpers ==================================
__device__ __forceinline__ uint32_t smem_u32(const void* p) {
    uint32_t a;
    asm("{ .reg .u64 t; cvta.to.shared.u64 t, %1; cvt.u32.u64 %0, t; }"
        : "=r"(a) : "l"(p));
    return a;
}
__device__ __forceinline__ void cp16(uint32_t dst, const void* src) {
    asm volatile("cp.async.cg.shared.global [%0], [%1], 16;" :: "r"(dst), "l"(src));
}
#define CP_COMMIT() asm volatile("cp.async.commit_group;" ::: "memory")
#define CP_WAIT(n)  asm volatile("cp.async.wait_group %0;" :: "n"(n) : "memory")

__device__ __forceinline__ void ldsm4(uint32_t* r, uint32_t addr) {
    asm volatile("ldmatrix.sync.aligned.m8n8.x4.shared.b16 {%0,%1,%2,%3}, [%4];"
                 : "=r"(r[0]), "=r"(r[1]), "=r"(r[2]), "=r"(r[3]) : "r"(addr));
}
__device__ __forceinline__ void mma_f16(float* d, const uint32_t* a, const uint32_t* b) {
    asm volatile(
        "mma.sync.aligned.m16n8k16.row.col.f32.f16.f16.f32 "
        "{%0,%1,%2,%3}, {%4,%5,%6,%7}, {%8,%9}, {%0,%1,%2,%3};"
        : "+f"(d[0]), "+f"(d[1]), "+f"(d[2]), "+f"(d[3])
        : "r"(a[0]), "r"(a[1]), "r"(a[2]), "r"(a[3]), "r"(b[0]), "r"(b[1]));
}
__device__ __forceinline__ uint32_t swz(uint32_t off) { return off ^ ((off >> 3) & 0x70); }

// ============================ fp16 2-way split =============================
__device__ __forceinline__ void split2h(float v, __half& h, __half& l) {
    h = __float2half(v);
    l = __float2half(v - __half2float(h));
}

// query -> [M][512] (hi | lo)
__global__ void split_query_kernel(const float* __restrict__ q) {
    size_t i = (size_t)(blockIdx.x * blockDim.x + threadIdx.x) * 4;
    float4 v = *(const float4*)&q[i];
    size_t row = i >> 8;
    int col = (int)(i & 255);
    __half h[4], l[4];
    split2h(v.x, h[0], l[0]); split2h(v.y, h[1], l[1]);
    split2h(v.z, h[2], l[2]); split2h(v.w, h[3], l[3]);
    __half* base = g_qs + row * KS + col;
    *(__half2*)(base)       = __half2(h[0], h[1]);
    *(__half2*)(base + 2)   = __half2(h[2], h[3]);
    *(__half2*)(base + 256) = __half2(l[0], l[1]);
    *(__half2*)(base + 258) = __half2(l[2], l[3]);
}

// wcat^T -> [128][512] padded with zero rows 96..127
__global__ void prep_wcat_kernel(const float* __restrict__ W_off,
                                 const float* __restrict__ b_off,
                                 const float* __restrict__ W_attn,
                                 const float* __restrict__ b_attn) {
    int id = blockIdx.x * blockDim.x + threadIdx.x;   // 128*256
    int j = id >> 8, k = id & 255;
    float v = 0.f;
    if (j < 64)       v = W_off[k * 64 + j];
    else if (j < 96)  v = W_attn[k * 32 + (j - 64)];
    __half h, l;
    split2h(v, h, l);
    g_wc[j * KS + k] = h; g_wc[j * KS + 256 + k] = l;
    if (id < P96) g_bcat[id] = (id < 64) ? b_off[id] : b_attn[id - 64];
}

// W_out^T -> [256][512]
__global__ void prep_wout_kernel(const float* __restrict__ W_out) {
    int id = blockIdx.x * blockDim.x + threadIdx.x;   // 256*256
    int n = id >> 8, k = id & 255;
    __half h, l;
    split2h(W_out[k * C_ + n], h, l);
    g_wo[n * KS + k] = h; g_wo[n * KS + 256 + k] = l;
}

// ---------------------------------------------------------------------------
// Transpose v4: (B, Hh*D, H*W) fp32 -> (B, Hh, H*W, D) fp16.
// XOR-swizzled float4 staging (conflict-free, 16B-aligned); phase 2 converts
// to __half and stores 8B per lane.
// ---------------------------------------------------------------------------
__global__ void transpose_val_kernel(const float* __restrict__ val) {
    __shared__ float4 t4[64][8];
    int bh = blockIdx.y;
    int p0 = blockIdx.x * 64;
    int tid = threadIdx.x;
    int dl = tid >> 6;         // 0..3
    int pl = tid & 63;         // 0..63
    const float* src = val + ((size_t)bh * 32) * HW_ + p0 + pl;
#pragma unroll
    for (int i = 0; i < 2; i++) {
        int dq = dl * 2 + i;   // 0..7
        float4 v;
        v.x = src[(size_t)(dq * 4 + 0) * HW_];
        v.y = src[(size_t)(dq * 4 + 1) * HW_];
        v.z = src[(size_t)(dq * 4 + 2) * HW_];
        v.w = src[(size_t)(dq * 4 + 3) * HW_];
        t4[pl][dq ^ (pl & 7)] = v;
    }
    __syncthreads();
    int c  = tid & 7;          // output d-quad
    int pw = tid >> 3;         // 0..31
    __half* dst = g_valth + (size_t)bh * HW_ * 32 + (size_t)p0 * 32;
#pragma unroll
    for (int i = 0; i < 2; i++) {
        int p = pw + i * 32;
        float4 v = t4[p][c ^ (p & 7)];
        __half2 h01 = __floats2half2_rn(v.x, v.y);
        __half2 h23 = __floats2half2_rn(v.z, v.w);
        uint2 u;
        u.x = *reinterpret_cast<uint32_t*>(&h01);
        u.y = *reinterpret_cast<uint32_t*>(&h23);
        *(uint2*)&dst[(size_t)p * 32 + c * 4] = u;
    }
}

// ===========================================================================
// fp16 mma.sync GEMM with error-compensated split products.
//   C = A_hi@B_hi^T + A_hi@B_lo^T + A_lo@B_hi^T  (+bias)
// One K=768 GEMM: chunk c reads A section {hi,hi,lo}[c/4], B {hi,lo,hi}[c/4].
// 128x128 CTA tile, 8 warps, warp tile 64x32, m16n8k16. 3-stage cp.async
// pipeline, one __syncthreads per chunk.
// ===========================================================================
template <int NSTORE, int LDC>
__global__ __launch_bounds__(256, 2)
void f16_gemm(const __half* __restrict__ A,
              const __half* __restrict__ BT,
              const float* __restrict__ bias,
              float* __restrict__ Cm) {
    extern __shared__ char dyn_raw[];
    const uint32_t raw = smem_u32(dyn_raw);
    const uint32_t sb  = (raw + 1023) & ~1023u;

    const int tid  = threadIdx.x;
    const int wid  = tid >> 5;
    const int lane = tid & 31;
    const int row0 = blockIdx.y * 128;
    const int col0 = blockIdx.x * 128;
    const int wm   = (wid >> 2) * 64;
    const int wn   = (wid & 3) * 32;

    float acc[4][4][4];
#pragma unroll
    for (int mi = 0; mi < 4; mi++)
#pragma unroll
        for (int ni = 0; ni < 4; ni++)
#pragma unroll
            for (int v = 0; v < 4; v++) acc[mi][ni][v] = 0.f;

    const int lrow = tid >> 3;          // 0..31 (x4 rows per iter)
    const int lblk = tid & 7;           // 16B chunk

    auto kA = [](int c) { const int s[3] = {0, 0, 256}; return s[c >> 2] + (c & 3) * 64; };
    auto kB = [](int c) { const int s[3] = {0, 256, 0}; return s[c >> 2] + (c & 3) * 64; };

    auto load_stage = [&](int c, int st) {
        uint32_t a_t = sb + st * 32768;
        uint32_t b_t = a_t + 16384;
        const __half* ag = A  + (size_t)(row0 + lrow) * KS + kA(c) + lblk * 8;
        const __half* bg = BT + (size_t)(col0 + lrow) * KS + kB(c) + lblk * 8;
#pragma unroll
        for (int i = 0; i < 4; i++) {
            int r = lrow + i * 32;
            cp16(a_t + swz(r * 128 + lblk * 16), ag + (size_t)i * 32 * KS);
            cp16(b_t + swz(r * 128 + lblk * 16), bg + (size_t)i * 32 * KS);
        }
        CP_COMMIT();
    };

    load_stage(0, 0);
    load_stage(1, 1);

    for (int c = 0; c < NKCH; c++) {
        if (c + 1 < NKCH) { CP_WAIT(1); } else { CP_WAIT(0); }
        __syncthreads();
        if (c + 2 < NKCH) load_stage(c + 2, (c + 2) % 3);

        const uint32_t a_t = sb + (c % 3) * 32768;
        const uint32_t b_t = a_t + 16384;
#pragma unroll
        for (int ks = 0; ks < 4; ks++) {
            uint32_t af[4][4];
#pragma unroll
            for (int mi = 0; mi < 4; mi++) {
                int r  = wm + mi * 16 + (lane & 15);
                int kc = ks * 16 + (lane >> 4) * 8;
                ldsm4(af[mi], a_t + swz(r * 128 + kc * 2));
            }
            uint32_t bf[4][2];
#pragma unroll
            for (int nj = 0; nj < 2; nj++) {
                int gsel = lane >> 3;
                int nrow = wn + (nj * 2 + (gsel >> 1)) * 8 + (lane & 7);
                int kc   = ks * 16 + (gsel & 1) * 8;
                uint32_t r4[4];
                ldsm4(r4, b_t + swz(nrow * 128 + kc * 2));
                bf[nj * 2][0]     = r4[0];
                bf[nj * 2][1]     = r4[1];
                bf[nj * 2 + 1][0] = r4[2];
                bf[nj * 2 + 1][1] = r4[3];
            }
#pragma unroll
            for (int mi = 0; mi < 4; mi++)
#pragma unroll
                for (int ni = 0; ni < 4; ni++)
                    mma_f16(acc[mi][ni], af[mi], bf[ni]);
        }
    }

    // ---- epilogue ----
    const int r = lane >> 2;
    const int q = lane & 3;
#pragma unroll
    for (int mi = 0; mi < 4; mi++) {
#pragma unroll
        for (int ni = 0; ni < 4; ni++) {
            int row = row0 + wm + mi * 16 + r;
            int c   = col0 + wn + ni * 8 + 2 * q;
            if (c < NSTORE) {
                float b0 = bias[c], b1 = bias[c + 1];
                float2 v0 = make_float2(acc[mi][ni][0] + b0, acc[mi][ni][1] + b1);
                float2 v1 = make_float2(acc[mi][ni][2] + b0, acc[mi][ni][3] + b1);
                *(float2*)&Cm[(size_t)row * LDC + c]       = v0;
                *(float2*)&Cm[(size_t)(row + 8) * LDC + c] = v1;
            }
        }
    }
}

// ---------------------------------------------------------------------------
// Sampling v3: HALF-WARP <-> (b, n, head) — 2 items per warp, halving the
// per-item redundant scalar work (softmax, coord math, issue slots).
// Within 16 lanes: corner g=(lane>>2)&3, lane loads uint4 = 8 halves
// (4 lanes x 16B = full 64B corner row). Compute-all/load-all/fma-all
// phases give MLP=4 across the point gathers. 2-round bfly reduction
// (xor 4, 8) stays inside the 16-lane group. Lanes g==0 write the fp16
// split of agg (16B-aligned uint4 stores).
// ---------------------------------------------------------------------------
__global__ void sample_kernel(const float* __restrict__ refp) {
    int gw   = (blockIdx.x * blockDim.x + threadIdx.x) >> 5;
    int lane = threadIdx.x & 31;
    int sub  = lane >> 4;                 // item within warp
    int it   = gw * 2 + sub;              // (b*N + n)*8 + h
    int h    = it & 7;
    int bn   = it >> 3;
    int b    = bn >> 13;

    int g  = (lane >> 2) & 3;             // bilinear corner
    int gx = g & 1, gy = g >> 1;
    int d8 = (lane & 3) * 8;              // halves offset

    const float* pr = g_params + (size_t)bn * P96;

    float bx = 2.f * refp[2 * bn];
    float by = 2.f * refp[2 * bn + 1];

    const float* al = pr + 64 + h * 4;
    float l0 = al[0], l1 = al[1], l2 = al[2], l3 = al[3];
    float mx = fmaxf(fmaxf(l0, l1), fmaxf(l2, l3));
    float e0 = __expf(l0 - mx), e1 = __expf(l1 - mx);
    float e2 = __expf(l2 - mx), e3 = __expf(l3 - mx);
    float inv = 1.f / (e0 + e1 + e2 + e3);
    float aw[4] = {e0 * inv, e1 * inv, e2 * inv, e3 * inv};

    const __half* vb = g_valth + (size_t)(b * NH_ + h) * HW_ * 32;

    // phase 1: all 4 points' corner weights + indices
    float wcv[4];
    int   idxv[4];
#pragma unroll
    for (int p = 0; p < 4; p++) {
        float ox = pr[(h * 4 + p) * 2];
        float oy = pr[(h * 4 + p) * 2 + 1];
        float x = fmaf(bx + ox, (float)W_ * 0.5f, -0.5f);
        float y = fmaf(by + oy, (float)H_ * 0.5f, -0.5f);
        float x0f = floorf(x), y0f = floorf(y);
        float wx = x - x0f, wy = y - y0f;
        int xc = (int)x0f + gx;
        int yc = (int)y0f + gy;
        float wcx = gx ? wx : 1.f - wx;
        float wcy = gy ? wy : 1.f - wy;
        bool valid = (xc >= 0) & (xc < W_) & (yc >= 0) & (yc < H_);
        wcv[p]  = valid ? (wcx * wcy * aw[p]) : 0.f;
        idxv[p] = valid ? (yc * W_ + xc) : 0;
    }
    // phase 2: all 4 gathers in flight
    uint4 vv[4];
#pragma unroll
    for (int p = 0; p < 4; p++)
        vv[p] = *(const uint4*)&vb[(size_t)idxv[p] * 32 + d8];
    // phase 3: convert + accumulate (8 channels per lane)
    float acc[8];
#pragma unroll
    for (int j = 0; j < 8; j++) acc[j] = 0.f;
#pragma unroll
    for (int p = 0; p < 4; p++) {
        float wc = wcv[p];
        const uint32_t* u = &vv[p].x;
#pragma unroll
        for (int j = 0; j < 4; j++) {
            float2 f = __half22float2(*reinterpret_cast<const __half2*>(&u[j]));
            acc[2 * j]     = fmaf(wc, f.x, acc[2 * j]);
            acc[2 * j + 1] = fmaf(wc, f.y, acc[2 * j + 1]);
        }
    }

    // reduce across corner groups (lanes l, l^4, l^8 within 16-lane item)
#pragma unroll
    for (int off = 4; off <= 8; off <<= 1)
#pragma unroll
        for (int j = 0; j < 8; j++)
            acc[j] += __shfl_xor_sync(0xffffffffu, acc[j], off);

    if (g == 0) {
        __half hh[8], ll[8];
#pragma unroll
        for (int j = 0; j < 8; j++) split2h(acc[j], hh[j], ll[j]);
        __half* base = g_as + (size_t)bn * KS + h * 32 + d8;
        uint4 uh, ul;
        uint32_t* ph = &uh.x;
        uint32_t* pl = &ul.x;
#pragma unroll
        for (int j = 0; j < 4; j++) {
            __half2 a(hh[2 * j], hh[2 * j + 1]);
            __half2 c(ll[2 * j], ll[2 * j + 1]);
            ph[j] = *reinterpret_cast<uint32_t*>(&a);
            pl[j] = *reinterpret_cast<uint32_t*>(&c);
        }
        *(uint4*)(base)       = uh;
        *(uint4*)(base + 256) = ul;
    }
}

// ---------------------------------------------------------------------------
extern "C" void kernel_launch(void* const* d_in, const int* in_sizes, int n_in,
                              void* d_out, int out_size) {
    const float* query  = (const float*)d_in[0];
    const float* refp   = (const float*)d_in[1];
    const float* value  = (const float*)d_in[2];
    const float* W_off  = (const float*)d_in[3];
    const float* b_off  = (const float*)d_in[4];
    const float* W_attn = (const float*)d_in[5];
    const float* b_attn = (const float*)d_in[6];
    const float* W_out  = (const float*)d_in[7];
    const float* b_out  = (const float*)d_in[8];
    float* out = (float*)d_out;

    __half *qs, *as, *wc, *wo;
    float *params, *bcat;
    cudaGetSymbolAddress((void**)&qs, g_qs);
    cudaGetSymbolAddress((void**)&as, g_as);
    cudaGetSymbolAddress((void**)&wc, g_wc);
    cudaGetSymbolAddress((void**)&wo, g_wo);
    cudaGetSymbolAddress((void**)&params, g_params);
    cudaGetSymbolAddress((void**)&bcat, g_bcat);

    const int SMEM = 3 * 32768 + 1024;   // 3-stage pipeline + align pad
    cudaFuncSetAttribute(f16_gemm<P96, P96>,
                         cudaFuncAttributeMaxDynamicSharedMemorySize, SMEM);
    cudaFuncSetAttribute(f16_gemm<C_, C_>,
                         cudaFuncAttributeMaxDynamicSharedMemorySize, SMEM);

    split_query_kernel<<<M_ * C_ / 4 / 256, 256>>>(query);
    prep_wcat_kernel<<<128 * C_ / 256, 256>>>(W_off, b_off, W_attn, b_attn);
    prep_wout_kernel<<<C_ * C_ / 256, 256>>>(W_out);
    transpose_val_kernel<<<dim3(HW_ / 64, B_ * NH_), 256>>>(value);

    // GEMM-1: params[M,96] = q_hi@w_hi + q_hi@w_lo + q_lo@w_hi + bcat
    f16_gemm<P96, P96><<<dim3(1, M_ / 128), 256, SMEM>>>(qs, wc, bcat, params);

    // 2 items per warp -> items/block = 16
    sample_kernel<<<(B_ * N_ * NH_) / 16, 256>>>(refp);

    // GEMM-2: out[M,256] = a_hi@wo_hi + a_hi@wo_lo + a_lo@wo_hi + b_out
    f16_gemm<C_, C_><<<dim3(2, M_ / 128), 256, SMEM>>>(as, wo, b_out, out);
}